// round 1
// baseline (speedup 1.0000x reference)
#include <cuda_runtime.h>
#include <cuda_bf16.h>

// LSTM: B=65536, T=20, I=36, H=30. Gate order i,f,g,o.
// Output layout: out[B,T,H] ++ h_n[1,B,H] ++ c_n[1,B,H] (flattened, fp32).

#define NB   65536
#define NT   20
#define NI   36
#define NH   30
#define G4   120          // 4*NH
#define WPAD 32           // W_hh row padded to 32 floats (128B) for LDS.128

__device__ __forceinline__ float sigmoid_f(float v) {
    // 1/(1+exp(-v)) via MUFU EX2 + RCP (rel err ~1e-6)
    return __fdividef(1.0f, 1.0f + __expf(-v));
}
__device__ __forceinline__ float tanh_f(float v) {
    // 2/(1+exp(-2v)) - 1 ; saturates correctly for large |v|
    return __fdividef(2.0f, 1.0f + __expf(-2.0f * v)) - 1.0f;
}

__global__ void __launch_bounds__(256, 2)
lstm_fused(const float* __restrict__ x,
           const float* __restrict__ W_ih,
           const float* __restrict__ W_hh,
           const float* __restrict__ b_ih,
           const float* __restrict__ b_hh,
           float* __restrict__ out) {
    __shared__ float sWih[G4 * NI];    // 4320 f, rows of 36 (144B, 16B-aligned)
    __shared__ float sWhh[G4 * WPAD];  // 3840 f, rows padded to 32 (zeros in pad)
    __shared__ float sB[G4];           // b_ih + b_hh

    const int tid = threadIdx.x;

    // Cooperative weight staging (all threads participate, then sync).
    for (int i = tid; i < G4 * NI; i += 256) sWih[i] = W_ih[i];
    for (int i = tid; i < G4 * WPAD; i += 256) {
        int r = i >> 5, c = i & 31;
        sWhh[i] = (c < NH) ? W_hh[r * NH + c] : 0.0f;
    }
    if (tid < G4) sB[tid] = b_ih[tid] + b_hh[tid];
    __syncthreads();

    // Interleaved batch mapping: every block gets ~222 active threads ->
    // perfectly balanced 2 CTAs per SM across all 296 blocks.
    const int b = blockIdx.x + (int)gridDim.x * tid;
    if (b >= NB) return;

    float h[WPAD];       // registers (all index loops fully unrolled); pad = 0
    float c[NH];         // local-mem (dynamic hh index), L1-resident
    float hn[NH];        // local-mem (dynamic hh index), L1-resident
#pragma unroll
    for (int j = 0; j < WPAD; j++) h[j] = 0.0f;
#pragma unroll
    for (int j = 0; j < NH; j++) c[j] = 0.0f;

    const float4* __restrict__ xb =
        reinterpret_cast<const float4*>(x + (size_t)b * (NT * NI));
    float* __restrict__ outb = out + (size_t)b * (NT * NH);
    float* __restrict__ hN = out + (size_t)NB * NT * NH + (size_t)b * NH;
    float* __restrict__ cN = hN + (size_t)NB * NH;

    for (int t = 0; t < NT; t++) {
        // x row for this timestep -> registers (9x LDG.128, aligned: 144B rows)
        float xr[NI];
#pragma unroll
        for (int q = 0; q < NI / 4; q++) {
            float4 v = xb[t * (NI / 4) + q];
            xr[4 * q + 0] = v.x; xr[4 * q + 1] = v.y;
            xr[4 * q + 2] = v.z; xr[4 * q + 3] = v.w;
        }

#pragma unroll 1   // keep rolled: body ~6KB fits L0 I$; full unroll = 173KB
        for (int hh = 0; hh < NH; hh++) {
            float a0 = sB[hh];
            float a1 = sB[NH + hh];
            float a2 = sB[2 * NH + hh];
            float a3 = sB[3 * NH + hh];

            const float4* w0 = reinterpret_cast<const float4*>(sWih + (0 * NH + hh) * NI);
            const float4* w1 = reinterpret_cast<const float4*>(sWih + (1 * NH + hh) * NI);
            const float4* w2 = reinterpret_cast<const float4*>(sWih + (2 * NH + hh) * NI);
            const float4* w3 = reinterpret_cast<const float4*>(sWih + (3 * NH + hh) * NI);
#pragma unroll
            for (int q = 0; q < NI / 4; q++) {
                float4 p0 = w0[q], p1 = w1[q], p2 = w2[q], p3 = w3[q];
                float x0 = xr[4 * q + 0], x1 = xr[4 * q + 1];
                float x2 = xr[4 * q + 2], x3 = xr[4 * q + 3];
                a0 = fmaf(x0, p0.x, a0); a0 = fmaf(x1, p0.y, a0);
                a0 = fmaf(x2, p0.z, a0); a0 = fmaf(x3, p0.w, a0);
                a1 = fmaf(x0, p1.x, a1); a1 = fmaf(x1, p1.y, a1);
                a1 = fmaf(x2, p1.z, a1); a1 = fmaf(x3, p1.w, a1);
                a2 = fmaf(x0, p2.x, a2); a2 = fmaf(x1, p2.y, a2);
                a2 = fmaf(x2, p2.z, a2); a2 = fmaf(x3, p2.w, a2);
                a3 = fmaf(x0, p3.x, a3); a3 = fmaf(x1, p3.y, a3);
                a3 = fmaf(x2, p3.z, a3); a3 = fmaf(x3, p3.w, a3);
            }

            const float4* v0 = reinterpret_cast<const float4*>(sWhh + (0 * NH + hh) * WPAD);
            const float4* v1 = reinterpret_cast<const float4*>(sWhh + (1 * NH + hh) * WPAD);
            const float4* v2 = reinterpret_cast<const float4*>(sWhh + (2 * NH + hh) * WPAD);
            const float4* v3 = reinterpret_cast<const float4*>(sWhh + (3 * NH + hh) * WPAD);
#pragma unroll
            for (int q = 0; q < WPAD / 4; q++) {  // pad weights are 0, h pad = 0
                float4 p0 = v0[q], p1 = v1[q], p2 = v2[q], p3 = v3[q];
                float h0 = h[4 * q + 0], h1 = h[4 * q + 1];
                float h2 = h[4 * q + 2], h3 = h[4 * q + 3];
                a0 = fmaf(h0, p0.x, a0); a0 = fmaf(h1, p0.y, a0);
                a0 = fmaf(h2, p0.z, a0); a0 = fmaf(h3, p0.w, a0);
                a1 = fmaf(h0, p1.x, a1); a1 = fmaf(h1, p1.y, a1);
                a1 = fmaf(h2, p1.z, a1); a1 = fmaf(h3, p1.w, a1);
                a2 = fmaf(h0, p2.x, a2); a2 = fmaf(h1, p2.y, a2);
                a2 = fmaf(h2, p2.z, a2); a2 = fmaf(h3, p2.w, a2);
                a3 = fmaf(h0, p3.x, a3); a3 = fmaf(h1, p3.y, a3);
                a3 = fmaf(h2, p3.z, a3); a3 = fmaf(h3, p3.w, a3);
            }

            float it = sigmoid_f(a0);
            float ft = sigmoid_f(a1);
            float gt = tanh_f(a2);
            float ot = sigmoid_f(a3);
            float cn = fmaf(ft, c[hh], it * gt);
            c[hh]  = cn;
            hn[hh] = ot * tanh_f(cn);
        }

        // h_new -> register h (unrolled constant-offset LDL), and emit output.
#pragma unroll
        for (int j = 0; j < NH; j++) h[j] = hn[j];

        float2* o2 = reinterpret_cast<float2*>(outb + t * NH);  // 8B-aligned
#pragma unroll
        for (int j = 0; j < NH / 2; j++)
            o2[j] = make_float2(h[2 * j], h[2 * j + 1]);
    }

    // Final states.
    float2* h2 = reinterpret_cast<float2*>(hN);
    float2* c2 = reinterpret_cast<float2*>(cN);
#pragma unroll
    for (int j = 0; j < NH / 2; j++) {
        h2[j] = make_float2(h[2 * j], h[2 * j + 1]);
        c2[j] = make_float2(c[2 * j], c[2 * j + 1]);
    }
}

extern "C" void kernel_launch(void* const* d_in, const int* in_sizes, int n_in,
                              void* d_out, int out_size) {
    const float* x    = (const float*)d_in[0];
    const float* W_ih = (const float*)d_in[1];
    const float* W_hh = (const float*)d_in[2];
    const float* b_ih = (const float*)d_in[3];
    const float* b_hh = (const float*)d_in[4];
    float* out = (float*)d_out;

    // 296 = 148 SMs * occupancy 2 -> every CTA resident, balanced load.
    lstm_fused<<<296, 256>>>(x, W_ih, W_hh, b_ih, b_hh, out);
}

// round 2
// speedup vs baseline: 1.2557x; 1.2557x over previous
#include <cuda_runtime.h>
#include <cuda_bf16.h>

// LSTM: B=65536, T=20, I=36, H=30. Gate order i,f,g,o.
// Output: out[B,T,H] ++ h_n[1,B,H] ++ c_n[1,B,H], fp32.
//
// Design: 2 batches per thread (weight-register reuse), warp owns 64
// contiguous batches, x/out staged through smem for coalesced gmem IO.

#define NB   65536
#define NT   20
#define NI   36
#define NH   30
#define G4   120
#define WPAD 32            // W_hh rows padded to 32 floats
#define XPAD 37            // stage-buffer row pitch (conflict-free: gcd(5,32)=1)

#define N_CHUNK 1024       // 65536 / 64 batches per warp
#define GRID    296
#define BLOCK   128

// smem float offsets
#define OFF_WIH  0
#define OFF_WHH  (G4 * NI)                   // 4320
#define OFF_B    (OFF_WHH + G4 * WPAD)       // 8160
#define OFF_STG  8288                        // 16B aligned, after 8280
#define STG_PER_WARP (64 * XPAD)             // 2368 floats
#define SMEM_FLOATS (OFF_STG + 4 * STG_PER_WARP)
#define SMEM_BYTES  (SMEM_FLOATS * 4)

__device__ __forceinline__ float sigmoid_f(float v) {
    return __fdividef(1.0f, 1.0f + __expf(-v));
}
__device__ __forceinline__ float tanh_f(float v) {
    return __fdividef(2.0f, 1.0f + __expf(-2.0f * v)) - 1.0f;
}

__global__ void __launch_bounds__(BLOCK, 2)
lstm_fused(const float* __restrict__ x,
           const float* __restrict__ W_ih,
           const float* __restrict__ W_hh,
           const float* __restrict__ b_ih,
           const float* __restrict__ b_hh,
           float* __restrict__ out) {
    extern __shared__ float sm[];
    float* sWih = sm + OFF_WIH;
    float* sWhh = sm + OFF_WHH;
    float* sB   = sm + OFF_B;

    const int tid  = threadIdx.x;
    const int wid  = tid >> 5;
    const int lane = tid & 31;

    // ---- cooperative weight staging ----
    for (int i = tid; i < G4 * NI; i += BLOCK) sWih[i] = W_ih[i];
    for (int i = tid; i < G4 * WPAD; i += BLOCK) {
        int r = i >> 5, c = i & 31;
        sWhh[i] = (c < NH) ? W_hh[r * NH + c] : 0.0f;
    }
    if (tid < G4) sB[tid] = b_ih[tid] + b_hh[tid];
    __syncthreads();

    // Warp chunk: C = wid*296 + bid  (keeps active-warp count balanced per SM)
    const int C = wid * GRID + blockIdx.x;
    if (C >= N_CHUNK) return;

    const int bbase = C * 64;            // warp's 64 contiguous batches
    const int b0 = bbase + lane;         // this thread's batch #0
    const int b1 = b0 + 32;              // this thread's batch #1

    float* wbuf = sm + OFF_STG + wid * STG_PER_WARP;   // 64 x 37 floats

    float h0[WPAD], h1[WPAD];            // registers (unrolled access); pad=0
    float c0[NH], c1[NH];                // local mem (dynamic hh index)
    float hn0[NH], hn1[NH];
#pragma unroll
    for (int j = 0; j < WPAD; j++) { h0[j] = 0.0f; h1[j] = 0.0f; }
#pragma unroll
    for (int j = 0; j < NH; j++) { c0[j] = 0.0f; c1[j] = 0.0f; }

    const float4* __restrict__ xg = reinterpret_cast<const float4*>(x);

    for (int t = 0; t < NT; t++) {
        // ---- coalesced x stage: 64 rows x 36 floats -> wbuf (pitch 37) ----
#pragma unroll
        for (int k = 0; k < 18; k++) {
            int i4 = lane + 32 * k;          // 0..575 = 64 rows * 9 float4
            int r  = i4 / 9;
            int c4 = i4 - r * 9;
            float4 v = xg[(size_t)(bbase + r) * (NT * NI / 4) + t * (NI / 4) + c4];
            float* d = wbuf + r * XPAD + c4 * 4;
            d[0] = v.x; d[1] = v.y; d[2] = v.z; d[3] = v.w;
        }
        __syncwarp();

        float xr0[NI], xr1[NI];
#pragma unroll
        for (int j = 0; j < NI; j++) xr0[j] = wbuf[lane * XPAD + j];
#pragma unroll
        for (int j = 0; j < NI; j++) xr1[j] = wbuf[(lane + 32) * XPAD + j];
        __syncwarp();   // buffer will be reused for output staging

#pragma unroll 1
        for (int hh = 0; hh < NH; hh++) {
            float a00 = sB[hh],          a01 = a00;
            float a10 = sB[NH + hh],     a11 = a10;
            float a20 = sB[2 * NH + hh], a21 = a20;
            float a30 = sB[3 * NH + hh], a31 = a30;

            const float4* w0 = reinterpret_cast<const float4*>(sWih + (0 * NH + hh) * NI);
            const float4* w1 = reinterpret_cast<const float4*>(sWih + (1 * NH + hh) * NI);
            const float4* w2 = reinterpret_cast<const float4*>(sWih + (2 * NH + hh) * NI);
            const float4* w3 = reinterpret_cast<const float4*>(sWih + (3 * NH + hh) * NI);
#pragma unroll
            for (int q = 0; q < NI / 4; q++) {
                float4 p0 = w0[q], p1 = w1[q], p2 = w2[q], p3 = w3[q];
                float u0 = xr0[4*q+0], u1 = xr0[4*q+1], u2 = xr0[4*q+2], u3 = xr0[4*q+3];
                float v0 = xr1[4*q+0], v1 = xr1[4*q+1], v2 = xr1[4*q+2], v3 = xr1[4*q+3];
                a00 = fmaf(u0,p0.x,a00); a00 = fmaf(u1,p0.y,a00); a00 = fmaf(u2,p0.z,a00); a00 = fmaf(u3,p0.w,a00);
                a01 = fmaf(v0,p0.x,a01); a01 = fmaf(v1,p0.y,a01); a01 = fmaf(v2,p0.z,a01); a01 = fmaf(v3,p0.w,a01);
                a10 = fmaf(u0,p1.x,a10); a10 = fmaf(u1,p1.y,a10); a10 = fmaf(u2,p1.z,a10); a10 = fmaf(u3,p1.w,a10);
                a11 = fmaf(v0,p1.x,a11); a11 = fmaf(v1,p1.y,a11); a11 = fmaf(v2,p1.z,a11); a11 = fmaf(v3,p1.w,a11);
                a20 = fmaf(u0,p2.x,a20); a20 = fmaf(u1,p2.y,a20); a20 = fmaf(u2,p2.z,a20); a20 = fmaf(u3,p2.w,a20);
                a21 = fmaf(v0,p2.x,a21); a21 = fmaf(v1,p2.y,a21); a21 = fmaf(v2,p2.z,a21); a21 = fmaf(v3,p2.w,a21);
                a30 = fmaf(u0,p3.x,a30); a30 = fmaf(u1,p3.y,a30); a30 = fmaf(u2,p3.z,a30); a30 = fmaf(u3,p3.w,a30);
                a31 = fmaf(v0,p3.x,a31); a31 = fmaf(v1,p3.y,a31); a31 = fmaf(v2,p3.z,a31); a31 = fmaf(v3,p3.w,a31);
            }

            const float4* q0 = reinterpret_cast<const float4*>(sWhh + (0 * NH + hh) * WPAD);
            const float4* q1 = reinterpret_cast<const float4*>(sWhh + (1 * NH + hh) * WPAD);
            const float4* q2 = reinterpret_cast<const float4*>(sWhh + (2 * NH + hh) * WPAD);
            const float4* q3 = reinterpret_cast<const float4*>(sWhh + (3 * NH + hh) * WPAD);
#pragma unroll
            for (int q = 0; q < WPAD / 4; q++) {
                float4 p0 = q0[q], p1 = q1[q], p2 = q2[q], p3 = q3[q];
                float u0 = h0[4*q+0], u1 = h0[4*q+1], u2 = h0[4*q+2], u3 = h0[4*q+3];
                float v0 = h1[4*q+0], v1 = h1[4*q+1], v2 = h1[4*q+2], v3 = h1[4*q+3];
                a00 = fmaf(u0,p0.x,a00); a00 = fmaf(u1,p0.y,a00); a00 = fmaf(u2,p0.z,a00); a00 = fmaf(u3,p0.w,a00);
                a01 = fmaf(v0,p0.x,a01); a01 = fmaf(v1,p0.y,a01); a01 = fmaf(v2,p0.z,a01); a01 = fmaf(v3,p0.w,a01);
                a10 = fmaf(u0,p1.x,a10); a10 = fmaf(u1,p1.y,a10); a10 = fmaf(u2,p1.z,a10); a10 = fmaf(u3,p1.w,a10);
                a11 = fmaf(v0,p1.x,a11); a11 = fmaf(v1,p1.y,a11); a11 = fmaf(v2,p1.z,a11); a11 = fmaf(v3,p1.w,a11);
                a20 = fmaf(u0,p2.x,a20); a20 = fmaf(u1,p2.y,a20); a20 = fmaf(u2,p2.z,a20); a20 = fmaf(u3,p2.w,a20);
                a21 = fmaf(v0,p2.x,a21); a21 = fmaf(v1,p2.y,a21); a21 = fmaf(v2,p2.z,a21); a21 = fmaf(v3,p2.w,a21);
                a30 = fmaf(u0,p3.x,a30); a30 = fmaf(u1,p3.y,a30); a30 = fmaf(u2,p3.z,a30); a30 = fmaf(u3,p3.w,a30);
                a31 = fmaf(v0,p3.x,a31); a31 = fmaf(v1,p3.y,a31); a31 = fmaf(v2,p3.z,a31); a31 = fmaf(v3,p3.w,a31);
            }

            {
                float it = sigmoid_f(a00), ft = sigmoid_f(a10);
                float gt = tanh_f(a20),    ot = sigmoid_f(a30);
                float cn = fmaf(ft, c0[hh], it * gt);
                c0[hh]  = cn;
                hn0[hh] = ot * tanh_f(cn);
            }
            {
                float it = sigmoid_f(a01), ft = sigmoid_f(a11);
                float gt = tanh_f(a21),    ot = sigmoid_f(a31);
                float cn = fmaf(ft, c1[hh], it * gt);
                c1[hh]  = cn;
                hn1[hh] = ot * tanh_f(cn);
            }
        }

        // h_new -> register h
#pragma unroll
        for (int j = 0; j < NH; j++) { h0[j] = hn0[j]; h1[j] = hn1[j]; }

        // ---- coalesced out stage: regs -> wbuf -> gmem ----
#pragma unroll
        for (int j = 0; j < NH; j++) {
            wbuf[lane * XPAD + j]        = h0[j];
            wbuf[(lane + 32) * XPAD + j] = h1[j];
        }
        __syncwarp();
#pragma unroll
        for (int k = 0; k < 60; k++) {
            int i = lane + 32 * k;           // 0..1919 = 64 rows * 30
            int r = i / 30;
            int c = i - r * 30;
            out[(size_t)(bbase + r) * (NT * NH) + t * NH + c] = wbuf[r * XPAD + c];
        }
        __syncwarp();                        // before next t reuses wbuf
    }

    // ---- final states (small, scattered OK) ----
    float* hN = out + (size_t)NB * NT * NH;
    float* cN = hN + (size_t)NB * NH;
#pragma unroll
    for (int j = 0; j < NH; j++) {
        hN[(size_t)b0 * NH + j] = h0[j];
        hN[(size_t)b1 * NH + j] = h1[j];
        cN[(size_t)b0 * NH + j] = c0[j];
        cN[(size_t)b1 * NH + j] = c1[j];
    }
}

extern "C" void kernel_launch(void* const* d_in, const int* in_sizes, int n_in,
                              void* d_out, int out_size) {
    const float* x    = (const float*)d_in[0];
    const float* W_ih = (const float*)d_in[1];
    const float* W_hh = (const float*)d_in[2];
    const float* b_ih = (const float*)d_in[3];
    const float* b_hh = (const float*)d_in[4];
    float* out = (float*)d_out;

    cudaFuncSetAttribute(lstm_fused,
                         cudaFuncAttributeMaxDynamicSharedMemorySize, SMEM_BYTES);
    lstm_fused<<<GRID, BLOCK, SMEM_BYTES>>>(x, W_ih, W_hh, b_ih, b_hh, out);
}